// round 9
// baseline (speedup 1.0000x reference)
#include <cuda_runtime.h>

// QLSTM: B=512, T=1024, IN=1, H=64.
// 128 blocks x 512 threads, 4 batches/block, persistent over all T.
// Lane bits: [0:1]=u-low(4), [2]=gs, [3:4]=ks (k-quarter). Warp id = u-high.
//   gs: gate split 0->{i,f}, 1->{g,o}.  ks: quarter of the 64-k contraction.
// Each thread handles ALL 4 batches. W slice = 2 gates x 16 k packed as
// 16 u64 (32 regs) -> register-resident under the 128-reg cap at TPB=512.
// fma.rn.f32x2 = 2 MACs/instr. h duplicated {h,h} in shared, double-buffered,
// quarters at 160B stride (bank groups 0/8/16/24 -> conflict-free LDS.128).
// Combine: SEL the two needed accs, butterfly xor8 (send other-parity acc),
// then xor16; gate exchange via xor4. bstar = 2*gs + ks_low owns (u,bstar);
// ks_high lanes duplicate the epilogue, only ks_high==0 writes (predicated).

#define TPB 512
#define NB  4
#define TSTEPS 1024
#define QSTR 20    // u64 per k-quarter: 16 data + 4 pad (160 B -> +8 banks)
#define BSTR 82    // u64 per batch row: 4*QSTR + 2

typedef unsigned long long u64t;

struct Smem {
  u64t hd[2][NB][BSTR];             // {h,h} dup, double-buffered: 5248 B
  union {
    float wstage[256 * 64];         // W_hh staging: 64 KB
    u64t  xsd[NB][TSTEPS];          // {x,x} dup input: 32 KB
  } un;
};

__device__ __forceinline__ u64t pack2(float lo, float hi) {
  u64t r;
  asm("mov.b64 %0, {%1, %2};" : "=l"(r) : "f"(lo), "f"(hi));
  return r;
}
__device__ __forceinline__ void unpack2(float& lo, float& hi, u64t v) {
  asm("mov.b64 {%0, %1}, %2;" : "=f"(lo), "=f"(hi) : "l"(v));
}
__device__ __forceinline__ u64t ffma2(u64t a, u64t b, u64t c) {
  u64t d;
  asm("fma.rn.f32x2 %0, %1, %2, %3;" : "=l"(d) : "l"(a), "l"(b), "l"(c));
  return d;
}
__device__ __forceinline__ u64t addx2(u64t a, u64t b) {
  u64t d;
  asm("add.rn.f32x2 %0, %1, %2;" : "=l"(d) : "l"(a), "l"(b));
  return d;
}
__device__ __forceinline__ u64t shflx(u64t v, int m) {
  return __shfl_xor_sync(0xFFFFFFFFu, v, m);
}

__device__ __forceinline__ float sigf(float v) {
  return __fdividef(1.0f, 1.0f + __expf(-v));
}
__device__ __forceinline__ float tanhf_fast(float v) {
  return 1.0f - __fdividef(2.0f, __expf(2.0f * v) + 1.0f);
}

extern __shared__ char smem_raw[];

__global__ void __launch_bounds__(TPB, 1) qlstm_kernel(
    const float* __restrict__ x,      // [B, T, 1]
    const float* __restrict__ W_ih,   // [256, 1]
    const float* __restrict__ W_hh,   // [256, 64]
    const float* __restrict__ b_ih,   // [256]
    const float* __restrict__ b_hh,   // [256]
    const float* __restrict__ W_lin,  // [1, 64]
    const float* __restrict__ b_lin,  // [1]
    float* __restrict__ out)          // [B]
{
  Smem& s = *reinterpret_cast<Smem*>(smem_raw);
  const int t   = threadIdx.x;
  const int ul  = t & 3;
  const int gs  = (t >> 2) & 1;       // lane bit 2
  const int ks  = (t >> 3) & 3;       // lane bits 3-4
  const int ksl = ks & 1;
  const int ksh = ks >> 1;
  const int uh  = t >> 5;             // warp id 0..15
  const int u   = ul + 4 * uh;        // 0..63
  const int bstar = 2 * gs + ksl;     // this lane's epilogue batch
  const int batch0 = blockIdx.x * NB;

  // ---- stage W_hh into shared (coalesced) ----
  {
    const float4* src = reinterpret_cast<const float4*>(W_hh);
    float4* dst = reinterpret_cast<float4*>(s.un.wstage);
    for (int i = t; i < 256 * 64 / 4; i += TPB) dst[i] = src[i];
  }
  __syncthreads();

  // ---- my W slice: 2 gates x 16 k packed (32 regs) ----
  const int r0 = gs * 128 + u;        // gate row i or g
  const int r1 = r0 + 64;             // gate row f or o
  const int k0 = 16 * ks;             // my k range [k0, k0+16)
  u64t Wreg[16];
#pragma unroll
  for (int kk = 0; kk < 16; kk++)
    Wreg[kk] = pack2(s.un.wstage[r0 * 64 + k0 + kk],
                     s.un.wstage[r1 * 64 + k0 + kk]);
  __syncthreads();                    // wstage dead; union reused for x

  // ---- stage x duplicated {x,x}; zero both h buffers ----
  for (int i = t; i < NB * TSTEPS; i += TPB) {
    int bb = i >> 10, tt = i & (TSTEPS - 1);
    float xv = x[(batch0 + bb) * TSTEPS + tt];
    s.un.xsd[bb][tt] = pack2(xv, xv);
  }
  for (int i = t; i < 2 * NB * BSTR; i += TPB)
    (&s.hd[0][0][0])[i] = 0ull;

  // bias + W_ih scaled by 1/4: every ks lane adds its share, the two
  // combine butterflies sum 4 shares -> full bias, no divergent branch.
  const u64t bias2 = pack2(0.25f * (b_ih[r0] + b_hh[r0]),
                           0.25f * (b_ih[r1] + b_hh[r1]));
  const u64t wih2  = pack2(0.25f * W_ih[r0], 0.25f * W_ih[r1]);
  __syncthreads();

  float c = 0.0f;                     // cell state for (u, bstar)
  int pb = 0;

  for (int step = 0; step < TSTEPS; step++) {
    u64t a0 = ffma2(wih2, s.un.xsd[0][step], bias2);
    u64t a1 = ffma2(wih2, s.un.xsd[1][step], bias2);
    u64t a2 = ffma2(wih2, s.un.xsd[2][step], bias2);
    u64t a3 = ffma2(wih2, s.un.xsd[3][step], bias2);

    // my k-quarter of h per batch; 4 distinct addrs/warp, bank-disjoint
    const ulonglong2* __restrict__ h0p =
        reinterpret_cast<const ulonglong2*>(&s.hd[pb][0][QSTR * ks]);
    const ulonglong2* __restrict__ h1p =
        reinterpret_cast<const ulonglong2*>(&s.hd[pb][1][QSTR * ks]);
    const ulonglong2* __restrict__ h2p =
        reinterpret_cast<const ulonglong2*>(&s.hd[pb][2][QSTR * ks]);
    const ulonglong2* __restrict__ h3p =
        reinterpret_cast<const ulonglong2*>(&s.hd[pb][3][QSTR * ks]);
#pragma unroll
    for (int j = 0; j < 8; j++) {
      ulonglong2 H0 = h0p[j];
      ulonglong2 H1 = h1p[j];
      ulonglong2 H2 = h2p[j];
      ulonglong2 H3 = h3p[j];
      u64t w0 = Wreg[2 * j], w1 = Wreg[2 * j + 1];
      a0 = ffma2(w0, H0.x, a0);
      a1 = ffma2(w0, H1.x, a1);
      a2 = ffma2(w0, H2.x, a2);
      a3 = ffma2(w0, H3.x, a3);
      a0 = ffma2(w1, H0.y, a0);
      a1 = ffma2(w1, H1.y, a1);
      a2 = ffma2(w1, H2.y, a2);
      a3 = ffma2(w1, H3.y, a3);
    }

    // Combine only the two accs this lane needs: batches {ksl, 2+ksl}.
    // xor8 flips ksl: keep my-parity accs, send other-parity (what the
    // partner needs); then xor16 (flips ksh) completes the 4-way sum.
    u64t v0 = ksl ? a1 : a0;          // batch ksl, partial
    u64t v1 = ksl ? a3 : a2;          // batch 2+ksl, partial
    u64t s0 = ksl ? a0 : a1;          // partner's batch, to send
    u64t s1 = ksl ? a2 : a3;
    v0 = addx2(v0, shflx(s0, 8));
    v1 = addx2(v1, shflx(s1, 8));
    v0 = addx2(v0, shflx(v0, 16));
    v1 = addx2(v1, shflx(v1, 16));

    // gate exchange with gs-partner (lane ^ 4): keep a[bstar]=my gates of
    // my batch, send a[bstar^2] (partner's batch, my gate pair).
    u64t mine   = gs ? v1 : v0;
    u64t tosend = gs ? v0 : v1;
    u64t partner = shflx(tosend, 4);

    float p0, p1, q0, q1;
    unpack2(p0, p1, mine);            // gs=0: {i,f}; gs=1: {g,o}
    unpack2(q0, q1, partner);         // other pair, SAME batch
    float iv, fv, gv, ov;
    if (gs == 0) { iv = p0; fv = p1; gv = q0; ov = q1; }
    else         { iv = q0; fv = q1; gv = p0; ov = p1; }

    iv = sigf(iv);
    fv = sigf(fv);
    gv = tanhf_fast(gv);
    ov = sigf(ov);
    c = fmaf(fv, c, iv * gv);
    float hn = ov * tanhf_fast(c);

    // one writer per (u, batch): ks_high == 0 lanes (predicated store)
    if (ksh == 0)
      s.hd[pb ^ 1][bstar][QSTR * (u >> 4) + (u & 15)] = pack2(hn, hn);
    pb ^= 1;
    __syncthreads();                  // double buffer -> one barrier
  }

  // final linear: out[b] = h_final[b] . W_lin + b_lin
  if (t < NB) {
    float sum = b_lin[0];
#pragma unroll
    for (int k = 0; k < 64; k++) {
      float lo, hi;
      unpack2(lo, hi, s.hd[pb][t][QSTR * (k >> 4) + (k & 15)]);
      sum = fmaf(lo, W_lin[k], sum);
    }
    out[batch0 + t] = sum;
  }
}

extern "C" void kernel_launch(void* const* d_in, const int* in_sizes, int n_in,
                              void* d_out, int out_size) {
  const float* x     = (const float*)d_in[0];
  const float* W_ih  = (const float*)d_in[1];
  const float* W_hh  = (const float*)d_in[2];
  const float* b_ih  = (const float*)d_in[3];
  const float* b_hh  = (const float*)d_in[4];
  const float* W_lin = (const float*)d_in[5];
  const float* b_lin = (const float*)d_in[6];
  float* out = (float*)d_out;

  const int B = out_size;  // 512
  const int nblocks = B / NB;

  cudaFuncSetAttribute(qlstm_kernel,
                       cudaFuncAttributeMaxDynamicSharedMemorySize,
                       (int)sizeof(Smem));
  qlstm_kernel<<<nblocks, TPB, sizeof(Smem)>>>(x, W_ih, W_hh, b_ih, b_hh,
                                               W_lin, b_lin, out);
}

// round 11
// speedup vs baseline: 1.3016x; 1.3016x over previous
#include <cuda_runtime.h>

// QLSTM: B=512, T=1024, IN=1, H=64.
// 128 blocks x 256 threads. Block = TWO INDEPENDENT groups of 128 threads;
// group g owns batches {2g, 2g+1} end-to-end and syncs only itself via a
// named barrier (bar.sync 1+g, 128). Groups share nothing in the main loop
// -> they drift out of phase, and each SMSP interleaves warps from both
// groups, hiding the per-step LDS/SHFL/MUFU/BAR dependency chain.
// Thread (u, gs) within a group: gs=0 -> gate rows {i,f}, gs=1 -> {g,o};
// W slice = 2 rows x 64 k packed as 64 u64 (128 regs, register-resident).
// fma.rn.f32x2 = 2 MACs/instr; 128 FFMA2/thread/step (2 batches).
// h duplicated {h,h} in shared (double-buffered); loads are uniform-address
// warp broadcasts. One u64 shfl_xor(1) swaps gate pairs; lane gs then owns
// batch (2g+gs): cell update in registers, one dup-u64 store, named barrier.

#define TPB 256
#define NB  4
#define TSTEPS 1024
#define HSTR 66   // u64 per batch row: 64 data + 2 pad

typedef unsigned long long u64t;

struct Smem {
  u64t hd[2][NB][HSTR];             // {h,h} dup, double-buffered
  union {
    float wstage[256 * 64];         // W_hh staging: 64 KB
    u64t  xsd[NB][TSTEPS];          // {x,x} dup input: 32 KB
  } un;
};

__device__ __forceinline__ u64t pack2(float lo, float hi) {
  u64t r;
  asm("mov.b64 %0, {%1, %2};" : "=l"(r) : "f"(lo), "f"(hi));
  return r;
}
__device__ __forceinline__ void unpack2(float& lo, float& hi, u64t v) {
  asm("mov.b64 {%0, %1}, %2;" : "=f"(lo), "=f"(hi) : "l"(v));
}
__device__ __forceinline__ u64t ffma2(u64t a, u64t b, u64t c) {
  u64t d;
  asm("fma.rn.f32x2 %0, %1, %2, %3;" : "=l"(d) : "l"(a), "l"(b), "l"(c));
  return d;
}
__device__ __forceinline__ u64t shflx(u64t v, int m) {
  return __shfl_xor_sync(0xFFFFFFFFu, v, m);
}

__device__ __forceinline__ float sigf(float v) {
  return __fdividef(1.0f, 1.0f + __expf(-v));
}
__device__ __forceinline__ float tanhf_fast(float v) {
  return 1.0f - __fdividef(2.0f, __expf(2.0f * v) + 1.0f);
}

extern __shared__ char smem_raw[];

__global__ void __launch_bounds__(TPB, 1) qlstm_kernel(
    const float* __restrict__ x,      // [B, T, 1]
    const float* __restrict__ W_ih,   // [256, 1]
    const float* __restrict__ W_hh,   // [256, 64]
    const float* __restrict__ b_ih,   // [256]
    const float* __restrict__ b_hh,   // [256]
    const float* __restrict__ W_lin,  // [1, 64]
    const float* __restrict__ b_lin,  // [1]
    float* __restrict__ out)          // [B]
{
  Smem& s = *reinterpret_cast<Smem*>(smem_raw);
  const int t   = threadIdx.x;
  const int grp = t >> 7;             // independent half-block 0/1
  const int tg  = t & 127;
  const int gs  = tg & 1;             // lane bit 0: gate split
  const int u   = tg >> 1;            // hidden unit 0..63
  const int b0  = 2 * grp;            // group's batches: b0, b0+1
  const int myb = b0 + gs;            // this lane's epilogue batch
  const int batch0 = blockIdx.x * NB;
  const int barid = 1 + grp;          // named barrier per group

  // ---- stage W_hh into shared (coalesced, whole block) ----
  {
    const float4* src = reinterpret_cast<const float4*>(W_hh);
    float4* dst = reinterpret_cast<float4*>(s.un.wstage);
    for (int i = t; i < 256 * 64 / 4; i += TPB) dst[i] = src[i];
  }
  __syncthreads();

  // ---- my W slice: 2 gate rows x full 64 k, packed (128 regs) ----
  const int r0 = gs * 128 + u;        // gate row i or g
  const int r1 = r0 + 64;             // gate row f or o
  u64t Wreg[64];
#pragma unroll
  for (int k = 0; k < 64; k++)
    Wreg[k] = pack2(s.un.wstage[r0 * 64 + k], s.un.wstage[r1 * 64 + k]);
  __syncthreads();                    // wstage dead; union reused for x

  // ---- stage x duplicated {x,x}; zero both h buffers ----
  for (int i = t; i < NB * TSTEPS; i += TPB) {
    int bb = i >> 10, tt = i & (TSTEPS - 1);
    float xv = x[(batch0 + bb) * TSTEPS + tt];
    s.un.xsd[bb][tt] = pack2(xv, xv);
  }
  for (int i = t; i < 2 * NB * HSTR; i += TPB)
    (&s.hd[0][0][0])[i] = 0ull;

  const u64t bias2 = pack2(b_ih[r0] + b_hh[r0], b_ih[r1] + b_hh[r1]);
  const u64t wih2  = pack2(W_ih[r0], W_ih[r1]);
  __syncthreads();                    // last full-block sync before the loop

  float c = 0.0f;                     // cell state for (u, myb)
  int pb = 0;

  for (int step = 0; step < TSTEPS; step++) {
    u64t a0 = ffma2(wih2, s.un.xsd[b0][step], bias2);      // batch b0
    u64t a1 = ffma2(wih2, s.un.xsd[b0 + 1][step], bias2);  // batch b0+1

    // h for my group's two batches; every address uniform across the warp
    const ulonglong2* __restrict__ h0p =
        reinterpret_cast<const ulonglong2*>(&s.hd[pb][b0][0]);
    const ulonglong2* __restrict__ h1p =
        reinterpret_cast<const ulonglong2*>(&s.hd[pb][b0 + 1][0]);
#pragma unroll
    for (int j = 0; j < 32; j++) {
      ulonglong2 H0 = h0p[j];         // {h_2j,h_2j, h_2j+1,h_2j+1}
      ulonglong2 H1 = h1p[j];
      u64t w0 = Wreg[2 * j], w1 = Wreg[2 * j + 1];
      a0 = ffma2(w0, H0.x, a0);
      a1 = ffma2(w0, H1.x, a1);
      a0 = ffma2(w1, H0.y, a0);
      a1 = ffma2(w1, H1.y, a1);
    }

    // gate exchange with gs-partner (lane ^ 1): keep my batch's pair,
    // send the other batch's pair (that is what the partner works on).
    u64t mine   = gs ? a1 : a0;
    u64t tosend = gs ? a0 : a1;
    u64t partner = shflx(tosend, 1);

    float p0, p1, q0, q1;
    unpack2(p0, p1, mine);            // gs=0: {i,f}; gs=1: {g,o}
    unpack2(q0, q1, partner);         // other pair, SAME batch (myb)
    float iv, fv, gv, ov;
    if (gs == 0) { iv = p0; fv = p1; gv = q0; ov = q1; }
    else         { iv = q0; fv = q1; gv = p0; ov = p1; }

    iv = sigf(iv);
    fv = sigf(fv);
    gv = tanhf_fast(gv);
    ov = sigf(ov);
    c = fmaf(fv, c, iv * gv);
    float hn = ov * tanhf_fast(c);

    s.hd[pb ^ 1][myb][u] = pack2(hn, hn);   // one writer per (u, batch)
    pb ^= 1;
    // group-private barrier: the two groups drift independently
    asm volatile("bar.sync %0, 128;" :: "r"(barid) : "memory");
  }

  __syncthreads();                    // re-converge both groups

  // final linear: out[b] = h_final[b] . W_lin + b_lin
  if (t < NB) {
    float sum = b_lin[0];
#pragma unroll
    for (int k = 0; k < 64; k++) {
      float lo, hi;
      unpack2(lo, hi, s.hd[pb][t][k]);
      sum = fmaf(lo, W_lin[k], sum);
    }
    out[batch0 + t] = sum;
  }
}

extern "C" void kernel_launch(void* const* d_in, const int* in_sizes, int n_in,
                              void* d_out, int out_size) {
  const float* x     = (const float*)d_in[0];
  const float* W_ih  = (const float*)d_in[1];
  const float* W_hh  = (const float*)d_in[2];
  const float* b_ih  = (const float*)d_in[3];
  const float* b_hh  = (const float*)d_in[4];
  const float* W_lin = (const float*)d_in[5];
  const float* b_lin = (const float*)d_in[6];
  float* out = (float*)d_out;

  const int B = out_size;  // 512
  const int nblocks = B / NB;

  cudaFuncSetAttribute(qlstm_kernel,
                       cudaFuncAttributeMaxDynamicSharedMemorySize,
                       (int)sizeof(Smem));
  qlstm_kernel<<<nblocks, TPB, sizeof(Smem)>>>(x, W_ih, W_hh, b_ih, b_hh,
                                               W_lin, b_lin, out);
}

// round 12
// speedup vs baseline: 1.5783x; 1.2125x over previous
#include <cuda_runtime.h>

// QLSTM: B=512, T=1024, IN=1, H=64.
// 128 blocks x 256 threads = TWO INDEPENDENT 128-thread groups; group g owns
// batches {2g, 2g+1} and syncs only itself (bar.sync 1+g, 128) -> groups run
// anti-phase, overlapping one group's epilogue with the other's math.
// Thread (u, gs) in a group: gs=0 -> gate rows {i,f}, gs=1 -> {g,o}; both of
// the group's batches. W for k in [0,32) is register-resident (32 u64 = 64
// regs, the proven no-spill budget); W for k in [32,64) streams from shared
// (wstream[k'][row]: lane-contiguous -> conflict-free LDS.64).
// fma.rn.f32x2 = 2 MACs/instr; two partial accumulators per batch halve the
// dependency chain. h duplicated {h,h} in shared (double-buffered, uniform-
// address broadcasts). One u64 shfl_xor(1) swaps gate pairs; lane gs owns
// batch 2g+gs end-to-end: cell update in regs, one dup-u64 store, named bar.

#define TPB 256
#define NB  4
#define TSTEPS 1024
#define HSTR 66     // u64 per batch row: 64 data + 2 pad

typedef unsigned long long u64t;

struct Smem {
  u64t hd[2][NB][HSTR];             // {h,h} dup, double-buffered
  u64t wstream[64][128];            // W pairs, k'=k-32 in [0,32) x row(tg)
                                    // [k'][row]; 64 slots (32 used) = 64 KB.. 32 KB
  union {
    float wstage[256 * 64];         // W_hh staging: 64 KB
    u64t  xsd[NB][TSTEPS];          // {x,x} dup input: 32 KB
  } un;
};

__device__ __forceinline__ u64t pack2(float lo, float hi) {
  u64t r;
  asm("mov.b64 %0, {%1, %2};" : "=l"(r) : "f"(lo), "f"(hi));
  return r;
}
__device__ __forceinline__ void unpack2(float& lo, float& hi, u64t v) {
  asm("mov.b64 {%0, %1}, %2;" : "=f"(lo), "=f"(hi) : "l"(v));
}
__device__ __forceinline__ u64t ffma2(u64t a, u64t b, u64t c) {
  u64t d;
  asm("fma.rn.f32x2 %0, %1, %2, %3;" : "=l"(d) : "l"(a), "l"(b), "l"(c));
  return d;
}
__device__ __forceinline__ u64t addx2(u64t a, u64t b) {
  u64t d;
  asm("add.rn.f32x2 %0, %1, %2;" : "=l"(d) : "l"(a), "l"(b));
  return d;
}
__device__ __forceinline__ u64t shflx(u64t v, int m) {
  return __shfl_xor_sync(0xFFFFFFFFu, v, m);
}

__device__ __forceinline__ float sigf(float v) {
  return __fdividef(1.0f, 1.0f + __expf(-v));
}
__device__ __forceinline__ float tanhf_fast(float v) {
  return 1.0f - __fdividef(2.0f, __expf(2.0f * v) + 1.0f);
}

extern __shared__ char smem_raw[];

__global__ void __launch_bounds__(TPB, 1) qlstm_kernel(
    const float* __restrict__ x,      // [B, T, 1]
    const float* __restrict__ W_ih,   // [256, 1]
    const float* __restrict__ W_hh,   // [256, 64]
    const float* __restrict__ b_ih,   // [256]
    const float* __restrict__ b_hh,   // [256]
    const float* __restrict__ W_lin,  // [1, 64]
    const float* __restrict__ b_lin,  // [1]
    float* __restrict__ out)          // [B]
{
  Smem& s = *reinterpret_cast<Smem*>(smem_raw);
  const int t   = threadIdx.x;
  const int grp = t >> 7;             // independent half-block 0/1
  const int tg  = t & 127;            // row id within group == W row id
  const int gs  = tg & 1;             // gate split
  const int u   = tg >> 1;            // hidden unit 0..63
  const int b0  = 2 * grp;            // group's batches: b0, b0+1
  const int myb = b0 + gs;            // this lane's epilogue batch
  const int batch0 = blockIdx.x * NB;
  const int barid = 1 + grp;

  // ---- stage W_hh into shared (coalesced, whole block) ----
  {
    const float4* src = reinterpret_cast<const float4*>(W_hh);
    float4* dst = reinterpret_cast<float4*>(s.un.wstage);
    for (int i = t; i < 256 * 64 / 4; i += TPB) dst[i] = src[i];
  }
  __syncthreads();

  // ---- W rows for this thread: r0 (i or g), r1 (f or o) ----
  const int r0 = gs * 128 + u;
  const int r1 = r0 + 64;

  // k in [0,32): registers (32 u64 = 64 regs, safe budget)
  u64t Wreg[32];
#pragma unroll
  for (int k = 0; k < 32; k++)
    Wreg[k] = pack2(s.un.wstage[r0 * 64 + k], s.un.wstage[r1 * 64 + k]);

  // k in [32,64): shared stream, lane-contiguous layout [k'][tg].
  // Both groups share one copy; rows are identical across groups.
  if (grp == 0) {
#pragma unroll
    for (int kq = 0; kq < 32; kq++)
      s.wstream[kq][tg] = pack2(s.un.wstage[r0 * 64 + 32 + kq],
                                s.un.wstage[r1 * 64 + 32 + kq]);
  }
  __syncthreads();                    // wstage dead; union reused for x

  // ---- stage x duplicated {x,x}; zero both h buffers ----
  for (int i = t; i < NB * TSTEPS; i += TPB) {
    int bb = i >> 10, tt = i & (TSTEPS - 1);
    float xv = x[(batch0 + bb) * TSTEPS + tt];
    s.un.xsd[bb][tt] = pack2(xv, xv);
  }
  for (int i = t; i < 2 * NB * HSTR; i += TPB)
    (&s.hd[0][0][0])[i] = 0ull;

  const u64t bias2 = pack2(b_ih[r0] + b_hh[r0], b_ih[r1] + b_hh[r1]);
  const u64t wih2  = pack2(W_ih[r0], W_ih[r1]);
  __syncthreads();                    // last full-block sync before the loop

  float c = 0.0f;                     // cell state for (u, myb)
  int pb = 0;

  for (int step = 0; step < TSTEPS; step++) {
    // two partial accs per batch -> half-length dependency chains
    u64t p0 = ffma2(wih2, s.un.xsd[b0][step], bias2);      // batch b0
    u64t p1 = ffma2(wih2, s.un.xsd[b0 + 1][step], bias2);  // batch b0+1
    u64t q0 = 0ull, q1 = 0ull;

    const ulonglong2* __restrict__ h0p =
        reinterpret_cast<const ulonglong2*>(&s.hd[pb][b0][0]);
    const ulonglong2* __restrict__ h1p =
        reinterpret_cast<const ulonglong2*>(&s.hd[pb][b0 + 1][0]);

    // k in [0,32): register W
#pragma unroll
    for (int j = 0; j < 16; j++) {
      ulonglong2 H0 = h0p[j];         // uniform address -> broadcast
      ulonglong2 H1 = h1p[j];
      u64t w0 = Wreg[2 * j], w1 = Wreg[2 * j + 1];
      p0 = ffma2(w0, H0.x, p0);
      p1 = ffma2(w0, H1.x, p1);
      q0 = ffma2(w1, H0.y, q0);
      q1 = ffma2(w1, H1.y, q1);
    }
    // k in [32,64): streamed W (lane-contiguous LDS.64, conflict-free)
#pragma unroll
    for (int j = 0; j < 16; j++) {
      ulonglong2 H0 = h0p[16 + j];
      ulonglong2 H1 = h1p[16 + j];
      u64t w0 = s.wstream[2 * j][tg];
      u64t w1 = s.wstream[2 * j + 1][tg];
      p0 = ffma2(w0, H0.x, p0);
      p1 = ffma2(w0, H1.x, p1);
      q0 = ffma2(w1, H0.y, q0);
      q1 = ffma2(w1, H1.y, q1);
    }
    u64t a0 = addx2(p0, q0);
    u64t a1 = addx2(p1, q1);

    // gate exchange with gs-partner (lane ^ 1): keep my batch's pair,
    // send the other batch's pair (what the partner works on).
    u64t mine   = gs ? a1 : a0;
    u64t tosend = gs ? a0 : a1;
    u64t partner = shflx(tosend, 1);

    float p0f, p1f, q0f, q1f;
    unpack2(p0f, p1f, mine);          // gs=0: {i,f}; gs=1: {g,o}
    unpack2(q0f, q1f, partner);       // other pair, SAME batch (myb)
    float iv, fv, gv, ov;
    if (gs == 0) { iv = p0f; fv = p1f; gv = q0f; ov = q1f; }
    else         { iv = q0f; fv = q1f; gv = p0f; ov = p1f; }

    iv = sigf(iv);
    fv = sigf(fv);
    gv = tanhf_fast(gv);
    ov = sigf(ov);
    c = fmaf(fv, c, iv * gv);
    float hn = ov * tanhf_fast(c);

    s.hd[pb ^ 1][myb][u] = pack2(hn, hn);   // one writer per (u, batch)
    pb ^= 1;
    // group-private barrier: the two groups drift independently
    asm volatile("bar.sync %0, 128;" :: "r"(barid) : "memory");
  }

  __syncthreads();                    // re-converge both groups

  // final linear: out[b] = h_final[b] . W_lin + b_lin
  if (t < NB) {
    float sum = b_lin[0];
#pragma unroll
    for (int k = 0; k < 64; k++) {
      float lo, hi;
      unpack2(lo, hi, s.hd[pb][t][k]);
      sum = fmaf(lo, W_lin[k], sum);
    }
    out[batch0 + t] = sum;
  }
}

extern "C" void kernel_launch(void* const* d_in, const int* in_sizes, int n_in,
                              void* d_out, int out_size) {
  const float* x     = (const float*)d_in[0];
  const float* W_ih  = (const float*)d_in[1];
  const float* W_hh  = (const float*)d_in[2];
  const float* b_ih  = (const float*)d_in[3];
  const float* b_hh  = (const float*)d_in[4];
  const float* W_lin = (const float*)d_in[5];
  const float* b_lin = (const float*)d_in[6];
  float* out = (float*)d_out;

  const int B = out_size;  // 512
  const int nblocks = B / NB;

  cudaFuncSetAttribute(qlstm_kernel,
                       cudaFuncAttributeMaxDynamicSharedMemorySize,
                       (int)sizeof(Smem));
  qlstm_kernel<<<nblocks, TPB, sizeof(Smem)>>>(x, W_ih, W_hh, b_ih, b_hh,
                                               W_lin, b_lin, out);
}

// round 14
// speedup vs baseline: 1.8129x; 1.1487x over previous
#include <cuda_runtime.h>

// QLSTM: B=512, T=1024, IN=1, H=64.
// 128 blocks x 256 threads, 4 batches/block, persistent over all T.
// Thread (u, ks): lane bits [0:1] = ks (k-quarter), [2:4] = u-low; u-high =
// warp id. Thread owns ALL 4 gate rows of unit u over k in [16ks, 16ks+16),
// for all 4 batches. k-PAIR FFMA2 packing: W{k,k+1} register pairs (4 gates
// x 8 pairs = 32 u64 = 64 regs, proven no-spill) times h{k,k+1} loaded as
// ulonglong2 from PLAIN contiguous h floats -> 16 LDS.128/thread/step
// (4x fewer than the dup-h scheme; LSU was the measured bottleneck).
// Accs hold {even-k, odd-k} partials; FADD folds. 2-level u64 butterfly over
// ks (xor1, xor2) with batch pruning -> lane ends with all 4 gates of
// (u, batch=ks): bias + W_ih*x post-combine, activations, c in regs, one
// STS.32. h double-buffered, quarters padded (20 floats) -> bank-disjoint.

#define TPB 256
#define NB  4
#define TSTEPS 1024
#define QF 20       // floats per k-quarter: 16 data + 4 pad

typedef unsigned long long u64t;

struct Smem {
  float hd[2][NB][4][QF];           // plain h, double-buffered: 2560 B
  union {
    float wstage[256 * 64];         // W_hh staging: 64 KB
    u64t  xsd[NB][TSTEPS];          // {x,x} dup input: 32 KB
  } un;
};

__device__ __forceinline__ u64t pack2(float lo, float hi) {
  u64t r;
  asm("mov.b64 %0, {%1, %2};" : "=l"(r) : "f"(lo), "f"(hi));
  return r;
}
__device__ __forceinline__ void unpack2(float& lo, float& hi, u64t v) {
  asm("mov.b64 {%0, %1}, %2;" : "=f"(lo), "=f"(hi) : "l"(v));
}
__device__ __forceinline__ u64t ffma2(u64t a, u64t b, u64t c) {
  u64t d;
  asm("fma.rn.f32x2 %0, %1, %2, %3;" : "=l"(d) : "l"(a), "l"(b), "l"(c));
  return d;
}
__device__ __forceinline__ u64t addx2(u64t a, u64t b) {
  u64t d;
  asm("add.rn.f32x2 %0, %1, %2;" : "=l"(d) : "l"(a), "l"(b));
  return d;
}
__device__ __forceinline__ u64t shflx(u64t v, int m) {
  return __shfl_xor_sync(0xFFFFFFFFu, v, m);
}

__device__ __forceinline__ float sigf(float v) {
  return __fdividef(1.0f, 1.0f + __expf(-v));
}
__device__ __forceinline__ float tanhf_fast(float v) {
  return 1.0f - __fdividef(2.0f, __expf(2.0f * v) + 1.0f);
}

extern __shared__ char smem_raw[];

__global__ void __launch_bounds__(TPB, 1) qlstm_kernel(
    const float* __restrict__ x,      // [B, T, 1]
    const float* __restrict__ W_ih,   // [256, 1]
    const float* __restrict__ W_hh,   // [256, 64]
    const float* __restrict__ b_ih,   // [256]
    const float* __restrict__ b_hh,   // [256]
    const float* __restrict__ W_lin,  // [1, 64]
    const float* __restrict__ b_lin,  // [1]
    float* __restrict__ out)          // [B]
{
  Smem& s = *reinterpret_cast<Smem*>(smem_raw);
  const int t   = threadIdx.x;
  const int ks  = t & 3;              // lane bits 0-1: k-quarter AND my batch
  const int ksl = ks & 1;
  const int ksh = ks >> 1;
  const int u   = t >> 2;             // hidden unit 0..63 (u-high = warp id)
  const int k0  = 16 * ks;            // my k range [k0, k0+16)
  const int batch0 = blockIdx.x * NB;

  // ---- stage W_hh into shared (coalesced) ----
  {
    const float4* src = reinterpret_cast<const float4*>(W_hh);
    float4* dst = reinterpret_cast<float4*>(s.un.wstage);
    for (int i = t; i < 256 * 64 / 4; i += TPB) dst[i] = src[i];
  }
  __syncthreads();

  // ---- my W slice: 4 gate rows x 8 k-pairs (32 u64 = 64 regs) ----
  // gate rows: i=u, f=64+u, g=128+u, o=192+u
  u64t Wreg[32];                      // [gate][pair] = Wreg[8*gate + p]
#pragma unroll
  for (int g = 0; g < 4; g++) {
    const float* row = &s.un.wstage[(64 * g + u) * 64 + k0];
#pragma unroll
    for (int p = 0; p < 8; p++)
      Wreg[8 * g + p] = pack2(row[2 * p], row[2 * p + 1]);
  }
  __syncthreads();                    // wstage dead; union reused for x

  // ---- stage x duplicated {x,x}; zero both h buffers ----
  for (int i = t; i < NB * TSTEPS; i += TPB) {
    int bb = i >> 10, tt = i & (TSTEPS - 1);
    float xv = x[(batch0 + bb) * TSTEPS + tt];
    s.un.xsd[bb][tt] = pack2(xv, xv);
  }
  for (int i = t; i < 2 * NB * 4 * QF; i += TPB)
    (&s.hd[0][0][0][0])[i] = 0.0f;

  // gate-pair constants for MY unit (used post-combine, batch = ks)
  const u64t bias_if = pack2(b_ih[u] + b_hh[u], b_ih[64 + u] + b_hh[64 + u]);
  const u64t bias_go = pack2(b_ih[128 + u] + b_hh[128 + u],
                             b_ih[192 + u] + b_hh[192 + u]);
  const u64t wih_if  = pack2(W_ih[u], W_ih[64 + u]);
  const u64t wih_go  = pack2(W_ih[128 + u], W_ih[192 + u]);
  __syncthreads();

  float c = 0.0f;                     // cell state for (u, batch ks)
  int pb = 0;

  for (int step = 0; step < TSTEPS; step++) {
    // 16 accs: A[gate][batch] = {even-k partial, odd-k partial}
    u64t A00 = 0, A01 = 0, A02 = 0, A03 = 0;   // gate i
    u64t A10 = 0, A11 = 0, A12 = 0, A13 = 0;   // gate f
    u64t A20 = 0, A21 = 0, A22 = 0, A23 = 0;   // gate g
    u64t A30 = 0, A31 = 0, A32 = 0, A33 = 0;   // gate o

    const ulonglong2* __restrict__ h0p =
        reinterpret_cast<const ulonglong2*>(&s.hd[pb][0][ks][0]);
    const ulonglong2* __restrict__ h1p =
        reinterpret_cast<const ulonglong2*>(&s.hd[pb][1][ks][0]);
    const ulonglong2* __restrict__ h2p =
        reinterpret_cast<const ulonglong2*>(&s.hd[pb][2][ks][0]);
    const ulonglong2* __restrict__ h3p =
        reinterpret_cast<const ulonglong2*>(&s.hd[pb][3][ks][0]);

#pragma unroll
    for (int j = 0; j < 4; j++) {     // 4 float4 = 16 k per batch
      ulonglong2 H0 = h0p[j];         // H.x = {h_k, h_k+1}: natural k-pairs
      ulonglong2 H1 = h1p[j];
      ulonglong2 H2 = h2p[j];
      ulonglong2 H3 = h3p[j];
      u64t wi0 = Wreg[2 * j],      wi1 = Wreg[2 * j + 1];
      u64t wf0 = Wreg[8 + 2 * j],  wf1 = Wreg[9 + 2 * j];
      u64t wg0 = Wreg[16 + 2 * j], wg1 = Wreg[17 + 2 * j];
      u64t wo0 = Wreg[24 + 2 * j], wo1 = Wreg[25 + 2 * j];
      A00 = ffma2(wi0, H0.x, A00); A00 = ffma2(wi1, H0.y, A00);
      A01 = ffma2(wi0, H1.x, A01); A01 = ffma2(wi1, H1.y, A01);
      A02 = ffma2(wi0, H2.x, A02); A02 = ffma2(wi1, H2.y, A02);
      A03 = ffma2(wi0, H3.x, A03); A03 = ffma2(wi1, H3.y, A03);
      A10 = ffma2(wf0, H0.x, A10); A10 = ffma2(wf1, H0.y, A10);
      A11 = ffma2(wf0, H1.x, A11); A11 = ffma2(wf1, H1.y, A11);
      A12 = ffma2(wf0, H2.x, A12); A12 = ffma2(wf1, H2.y, A12);
      A13 = ffma2(wf0, H3.x, A13); A13 = ffma2(wf1, H3.y, A13);
      A20 = ffma2(wg0, H0.x, A20); A20 = ffma2(wg1, H0.y, A20);
      A21 = ffma2(wg0, H1.x, A21); A21 = ffma2(wg1, H1.y, A21);
      A22 = ffma2(wg0, H2.x, A22); A22 = ffma2(wg1, H2.y, A22);
      A23 = ffma2(wg0, H3.x, A23); A23 = ffma2(wg1, H3.y, A23);
      A30 = ffma2(wo0, H0.x, A30); A30 = ffma2(wo1, H0.y, A30);
      A31 = ffma2(wo0, H1.x, A31); A31 = ffma2(wo1, H1.y, A31);
      A32 = ffma2(wo0, H2.x, A32); A32 = ffma2(wo1, H2.y, A32);
      A33 = ffma2(wo0, H3.x, A33); A33 = ffma2(wo1, H3.y, A33);
    }

    // fold even/odd partials -> S[gate][batch]; pack gate pairs:
    // P0[b] = {i,f} partial, P1[b] = {g,o} partial
    u64t P0[4], P1[4];
#pragma unroll
    for (int b = 0; b < 4; b++) {
      u64t ai = (b == 0) ? A00 : (b == 1) ? A01 : (b == 2) ? A02 : A03;
      u64t af = (b == 0) ? A10 : (b == 1) ? A11 : (b == 2) ? A12 : A13;
      u64t ag = (b == 0) ? A20 : (b == 1) ? A21 : (b == 2) ? A22 : A23;
      u64t ao = (b == 0) ? A30 : (b == 1) ? A31 : (b == 2) ? A32 : A33;
      float xi, yi, xf, yf, xg, yg, xo, yo;
      unpack2(xi, yi, ai);
      unpack2(xf, yf, af);
      unpack2(xg, yg, ag);
      unpack2(xo, yo, ao);
      P0[b] = pack2(xi + yi, xf + yf);
      P1[b] = pack2(xg + yg, xo + yo);
    }

    // butterfly 1 (xor1, flips ksl): keep batches with b&1==ksl,
    // send the complementary ones (what the partner keeps).
    u64t Q0 = addx2(P0[ksl],     shflx(P0[1 - ksl], 1));  // {i,f} b=ksl
    u64t Q1 = addx2(P1[ksl],     shflx(P1[1 - ksl], 1));  // {g,o} b=ksl
    u64t Q2 = addx2(P0[2 + ksl], shflx(P0[3 - ksl], 1));  // {i,f} b=2+ksl
    u64t Q3 = addx2(P1[2 + ksl], shflx(P1[3 - ksl], 1));  // {g,o} b=2+ksl

    // butterfly 2 (xor2, flips ksh): keep batch ks = 2*ksh+ksl
    u64t R0 = addx2(ksh ? Q2 : Q0, shflx(ksh ? Q0 : Q2, 2));  // {i,f} b=ks
    u64t R1 = addx2(ksh ? Q3 : Q1, shflx(ksh ? Q1 : Q3, 2));  // {g,o} b=ks

    // bias + W_ih * x (batch ks), once, post-combine
    u64t xd = s.un.xsd[ks][step];
    R0 = ffma2(wih_if, xd, addx2(R0, bias_if));
    R1 = ffma2(wih_go, xd, addx2(R1, bias_go));

    float iv, fv, gv, ov;
    unpack2(iv, fv, R0);
    unpack2(gv, ov, R1);
    iv = sigf(iv);
    fv = sigf(fv);
    gv = tanhf_fast(gv);
    ov = sigf(ov);
    c = fmaf(fv, c, iv * gv);
    float hn = ov * tanhf_fast(c);

    // every thread writes exactly its (u, batch ks) h value
    s.hd[pb ^ 1][ks][u >> 4][u & 15] = hn;
    pb ^= 1;
    __syncthreads();                  // double buffer -> one barrier
  }

  // final linear: out[b] = h_final[b] . W_lin + b_lin
  if (t < NB) {
    float sum = b_lin[0];
#pragma unroll
    for (int k = 0; k < 64; k++)
      sum = fmaf(s.hd[pb][t][k >> 4][k & 15], W_lin[k], sum);
    out[batch0 + t] = sum;
  }
}

extern "C" void kernel_launch(void* const* d_in, const int* in_sizes, int n_in,
                              void* d_out, int out_size) {
  const float* x     = (const float*)d_in[0];
  const float* W_ih  = (const float*)d_in[1];
  const float* W_hh  = (const float*)d_in[2];
  const float* b_ih  = (const float*)d_in[3];
  const float* b_hh  = (const float*)d_in[4];
  const float* W_lin = (const float*)d_in[5];
  const float* b_lin = (const float*)d_in[6];
  float* out = (float*)d_out;

  const int B = out_size;  // 512
  const int nblocks = B / NB;

  cudaFuncSetAttribute(qlstm_kernel,
                       cudaFuncAttributeMaxDynamicSharedMemorySize,
                       (int)sizeof(Smem));
  qlstm_kernel<<<nblocks, TPB, sizeof(Smem)>>>(x, W_ih, W_hh, b_ih, b_hh,
                                               W_lin, b_lin, out);
}

// round 17
// speedup vs baseline: 2.0326x; 1.1212x over previous
#include <cuda_runtime.h>

// QLSTM: B=512, T=1024, IN=1, H=64.
// 256 blocks x 256 threads, NB=2 batches/block, TWO CTAs CO-RESIDENT PER SM
// (__launch_bounds__(256,2)); the two CTAs are independent barrier domains,
// so their phases interleave on each SMSP and hide each other's serial
// epilogue chain (the measured ~1000-cyc/step exposed-latency floor of all
// single-CTA variants).
// Thread (u, ks): lane bits [0:1] = ks (k-quarter), u = t>>2. Thread owns
// ALL 4 gate rows of unit u over k in [16ks,16ks+16) for both batches.
// k-PAIR FFMA2 packing: W{k,k+1} register pairs (4 gates x 8 pairs = 32 u64
// = 64 regs) x h{k,k+1} loaded as ulonglong2 from plain contiguous h floats
// -> only 8 LDS.128/thread/step. Accs hold {even,odd} k partials; FADD folds.
// 2-level u64 butterfly (xor1 prunes to batch ksl, xor2 completes the
// 4-quarter sum); both ksh twins compute the epilogue identically (c is
// redundant-identical), only ksh==0 stores. One barrier per step.

#define TPB 256
#define NB  2
#define TSTEPS 1024
#define QF 20       // floats per k-quarter: 16 data + 4 pad (bank-disjoint)

typedef unsigned long long u64t;

struct Smem {
  float hd[2][NB][4][QF];           // plain h, double-buffered: 640 B
  union {
    float wstage[256 * 64];         // W_hh staging: 64 KB
    u64t  xsd[NB][TSTEPS];          // {x,x} dup input: 16 KB
  } un;
};

__device__ __forceinline__ u64t pack2(float lo, float hi) {
  u64t r;
  asm("mov.b64 %0, {%1, %2};" : "=l"(r) : "f"(lo), "f"(hi));
  return r;
}
__device__ __forceinline__ void unpack2(float& lo, float& hi, u64t v) {
  asm("mov.b64 {%0, %1}, %2;" : "=f"(lo), "=f"(hi) : "l"(v));
}
__device__ __forceinline__ u64t ffma2(u64t a, u64t b, u64t c) {
  u64t d;
  asm("fma.rn.f32x2 %0, %1, %2, %3;" : "=l"(d) : "l"(a), "l"(b), "l"(c));
  return d;
}
__device__ __forceinline__ u64t addx2(u64t a, u64t b) {
  u64t d;
  asm("add.rn.f32x2 %0, %1, %2;" : "=l"(d) : "l"(a), "l"(b));
  return d;
}
__device__ __forceinline__ u64t shflx(u64t v, int m) {
  return __shfl_xor_sync(0xFFFFFFFFu, v, m);
}

__device__ __forceinline__ float sigf(float v) {
  return __fdividef(1.0f, 1.0f + __expf(-v));
}
__device__ __forceinline__ float tanhf_fast(float v) {
  return 1.0f - __fdividef(2.0f, __expf(2.0f * v) + 1.0f);
}

extern __shared__ char smem_raw[];

__global__ void __launch_bounds__(TPB, 2) qlstm_kernel(
    const float* __restrict__ x,      // [B, T, 1]
    const float* __restrict__ W_ih,   // [256, 1]
    const float* __restrict__ W_hh,   // [256, 64]
    const float* __restrict__ b_ih,   // [256]
    const float* __restrict__ b_hh,   // [256]
    const float* __restrict__ W_lin,  // [1, 64]
    const float* __restrict__ b_lin,  // [1]
    float* __restrict__ out)          // [B]
{
  Smem& s = *reinterpret_cast<Smem*>(smem_raw);
  const int t   = threadIdx.x;
  const int ks  = t & 3;              // k-quarter
  const int ksl = ks & 1;             // my epilogue batch
  const int ksh = ks >> 1;            // epilogue twin id
  const int u   = t >> 2;             // hidden unit 0..63
  const int k0  = 16 * ks;            // my k range [k0, k0+16)
  const int batch0 = blockIdx.x * NB;

  // ---- stage W_hh into shared (coalesced) ----
  {
    const float4* src = reinterpret_cast<const float4*>(W_hh);
    float4* dst = reinterpret_cast<float4*>(s.un.wstage);
    for (int i = t; i < 256 * 64 / 4; i += TPB) dst[i] = src[i];
  }
  __syncthreads();

  // ---- my W slice: 4 gate rows x 8 k-pairs (32 u64 = 64 regs) ----
  u64t Wreg[32];                      // [gate][pair] = Wreg[8*gate + p]
#pragma unroll
  for (int g = 0; g < 4; g++) {
    const float* row = &s.un.wstage[(64 * g + u) * 64 + k0];
#pragma unroll
    for (int p = 0; p < 8; p++)
      Wreg[8 * g + p] = pack2(row[2 * p], row[2 * p + 1]);
  }
  __syncthreads();                    // wstage dead; union reused for x

  // ---- stage x duplicated {x,x}; zero both h buffers ----
  for (int i = t; i < NB * TSTEPS; i += TPB) {
    int bb = i >> 10, tt = i & (TSTEPS - 1);
    float xv = x[(batch0 + bb) * TSTEPS + tt];
    s.un.xsd[bb][tt] = pack2(xv, xv);
  }
  for (int i = t; i < 2 * NB * 4 * QF; i += TPB)
    (&s.hd[0][0][0][0])[i] = 0.0f;

  // gate-pair constants (used post-combine, batch = ksl)
  const u64t bias_if = pack2(b_ih[u] + b_hh[u], b_ih[64 + u] + b_hh[64 + u]);
  const u64t bias_go = pack2(b_ih[128 + u] + b_hh[128 + u],
                             b_ih[192 + u] + b_hh[192 + u]);
  const u64t wih_if  = pack2(W_ih[u], W_ih[64 + u]);
  const u64t wih_go  = pack2(W_ih[128 + u], W_ih[192 + u]);
  __syncthreads();

  float c = 0.0f;                     // cell state for (u, batch ksl)
  int pb = 0;

  for (int step = 0; step < TSTEPS; step++) {
    // 8 accs: A[gate][batch] = {even-k partial, odd-k partial}
    u64t A00 = 0, A01 = 0;            // gate i, batches 0,1
    u64t A10 = 0, A11 = 0;            // gate f
    u64t A20 = 0, A21 = 0;            // gate g
    u64t A30 = 0, A31 = 0;            // gate o

    const ulonglong2* __restrict__ h0p =
        reinterpret_cast<const ulonglong2*>(&s.hd[pb][0][ks][0]);
    const ulonglong2* __restrict__ h1p =
        reinterpret_cast<const ulonglong2*>(&s.hd[pb][1][ks][0]);

#pragma unroll
    for (int j = 0; j < 4; j++) {     // 4 x (4 k-pairs) = 16 k per batch
      ulonglong2 H0 = h0p[j];         // {h_k,h_k+1},{h_k+2,h_k+3}
      ulonglong2 H1 = h1p[j];
      u64t wi0 = Wreg[2 * j],      wi1 = Wreg[2 * j + 1];
      u64t wf0 = Wreg[8 + 2 * j],  wf1 = Wreg[9 + 2 * j];
      u64t wg0 = Wreg[16 + 2 * j], wg1 = Wreg[17 + 2 * j];
      u64t wo0 = Wreg[24 + 2 * j], wo1 = Wreg[25 + 2 * j];
      A00 = ffma2(wi0, H0.x, A00); A00 = ffma2(wi1, H0.y, A00);
      A01 = ffma2(wi0, H1.x, A01); A01 = ffma2(wi1, H1.y, A01);
      A10 = ffma2(wf0, H0.x, A10); A10 = ffma2(wf1, H0.y, A10);
      A11 = ffma2(wf0, H1.x, A11); A11 = ffma2(wf1, H1.y, A11);
      A20 = ffma2(wg0, H0.x, A20); A20 = ffma2(wg1, H0.y, A20);
      A21 = ffma2(wg0, H1.x, A21); A21 = ffma2(wg1, H1.y, A21);
      A30 = ffma2(wo0, H0.x, A30); A30 = ffma2(wo1, H0.y, A30);
      A31 = ffma2(wo0, H1.x, A31); A31 = ffma2(wo1, H1.y, A31);
    }

    // fold even/odd partials; pack gate pairs per batch:
    // P0[b] = {i,f} partial, P1[b] = {g,o} partial
    u64t P0[2], P1[2];
#pragma unroll
    for (int b = 0; b < 2; b++) {
      u64t ai = b ? A01 : A00;
      u64t af = b ? A11 : A10;
      u64t ag = b ? A21 : A20;
      u64t ao = b ? A31 : A30;
      float xi, yi, xf, yf, xg, yg, xo, yo;
      unpack2(xi, yi, ai);
      unpack2(xf, yf, af);
      unpack2(xg, yg, ag);
      unpack2(xo, yo, ao);
      P0[b] = pack2(xi + yi, xf + yf);
      P1[b] = pack2(xg + yg, xo + yo);
    }

    // butterfly 1 (xor1, flips ksl): keep batch ksl, send batch 1-ksl
    u64t Q0 = addx2(P0[ksl], shflx(P0[1 - ksl], 1));  // {i,f} b=ksl
    u64t Q1 = addx2(P1[ksl], shflx(P1[1 - ksl], 1));  // {g,o} b=ksl
    // butterfly 2 (xor2, flips ksh; partner has same batch)
    u64t R0 = addx2(Q0, shflx(Q0, 2));
    u64t R1 = addx2(Q1, shflx(Q1, 2));

    // bias + W_ih * x (batch ksl), once, post-combine
    u64t xd = s.un.xsd[ksl][step];
    R0 = ffma2(wih_if, xd, addx2(R0, bias_if));
    R1 = ffma2(wih_go, xd, addx2(R1, bias_go));

    float iv, fv, gv, ov;
    unpack2(iv, fv, R0);
    unpack2(gv, ov, R1);
    iv = sigf(iv);
    fv = sigf(fv);
    gv = tanhf_fast(gv);
    ov = sigf(ov);
    c = fmaf(fv, c, iv * gv);         // ksh twins: bit-identical c
    float hn = ov * tanhf_fast(c);

    if (ksh == 0)                     // one writer per (u, batch)
      s.hd[pb ^ 1][ksl][u >> 4][u & 15] = hn;
    pb ^= 1;
    __syncthreads();                  // double buffer -> one barrier
  }

  // final linear: out[b] = h_final[b] . W_lin + b_lin
  if (t < NB) {
    float sum = b_lin[0];
#pragma unroll
    for (int k = 0; k < 64; k++)
      sum = fmaf(s.hd[pb][t][k >> 4][k & 15], W_lin[k], sum);
    out[batch0 + t] = sum;
  }
}

extern "C" void kernel_launch(void* const* d_in, const int* in_sizes, int n_in,
                              void* d_out, int out_size) {
  const float* x     = (const float*)d_in[0];
  const float* W_ih  = (const float*)d_in[1];
  const float* W_hh  = (const float*)d_in[2];
  const float* b_ih  = (const float*)d_in[3];
  const float* b_hh  = (const float*)d_in[4];
  const float* W_lin = (const float*)d_in[5];
  const float* b_lin = (const float*)d_in[6];
  float* out = (float*)d_out;

  const int B = out_size;  // 512
  const int nblocks = B / NB;         // 256 -> 2 CTAs per SM

  cudaFuncSetAttribute(qlstm_kernel,
                       cudaFuncAttributeMaxDynamicSharedMemorySize,
                       (int)sizeof(Smem));
  qlstm_kernel<<<nblocks, TPB, sizeof(Smem)>>>(x, W_ih, W_hh, b_ih, b_hh,
                                               W_lin, b_lin, out);
}